// round 1
// baseline (speedup 1.0000x reference)
#include <cuda_runtime.h>
#include <math.h>

// ---------------------------------------------------------------------------
// Problem constants
// ---------------------------------------------------------------------------
#define BATCH    256
#define RESOL    14
#define NTOK     196      // RES*RES
#define NQTOK    49       // 7*7
#define INDIM    384
#define HEADS    12
#define KD       16
#define VD       32
#define KVD      576      // HEADS*(KD+VD)
#define KEYATTN  192      // HEADS*KD
#define VALATTN  384      // HEADS*VD
#define OUTDIM   512
#define ATTNSCALE 0.25f   // KD^-0.5
#define BN_EPS   1e-5f

#define M1 (BATCH*NTOK)   // 50176
#define M2 (BATCH*NQTOK)  // 12544

// Scratch (device globals -- no allocation allowed)
__device__ float g_kv[(size_t)M1 * KVD];     // [B*N, 576]
__device__ float g_q [(size_t)M2 * KEYATTN]; // [B*NQ, 192]
__device__ float g_ao[(size_t)M2 * VALATTN]; // [B*NQ, 384] (post-silu)

// ---------------------------------------------------------------------------
// GEMM + BatchNorm epilogue.
// C[m,n] = (sum_k A[m,k]*W[n,k] - mean[n]) * g[n]*rsqrt(v[n]+eps) + b[n]
// A row-major [M,384], W row-major [N,384]. K=384 fixed.
// Tile: BM=128, BN=64, BK=16, 256 threads, 8x4 per-thread microtile.
// GATHER: A logical row m maps to x row b*196 + (qi*2)*14 + qj*2 (downsample).
// ---------------------------------------------------------------------------
template<bool GATHER>
__global__ __launch_bounds__(256)
void gemm_bn_kernel(const float* __restrict__ A, const float* __restrict__ W,
                    const float* __restrict__ bn_g, const float* __restrict__ bn_b,
                    const float* __restrict__ bn_m, const float* __restrict__ bn_v,
                    float* __restrict__ C, int N)
{
    const int K = INDIM;
    __shared__ float As[16][132];   // [k][m], padded
    __shared__ float Bs[16][68];    // [k][n], padded

    const int tid = threadIdx.x;
    const int bm  = blockIdx.y * 128;
    const int bn  = blockIdx.x * 64;
    const int tx  = tid & 15;       // n dir, covers 64 (TN=4)
    const int ty  = tid >> 4;       // m dir, covers 128 (TM=8)

    // A-tile load mapping: 512 float4 per tile -> 2 per thread.
    const int akq   = tid & 3;       // which float4 within a 16-float row
    const int arow0 = tid >> 2;      // rows arow0, arow0+64
    int asrc[2];
#pragma unroll
    for (int r = 0; r < 2; r++) {
        int m = bm + arow0 + r * 64;
        if (GATHER) {
            int b  = m / NQTOK;
            int qq = m - b * NQTOK;
            int qi = qq / 7;
            int qj = qq - qi * 7;
            asrc[r] = b * NTOK + qi * 2 * RESOL + qj * 2;
        } else {
            asrc[r] = m;
        }
    }
    const int brow = tid >> 2;       // 64 rows, 4 float4 each -> 1 per thread
    const int bsrc = bn + brow;

    float acc[8][4] = {};

    for (int k0 = 0; k0 < K; k0 += 16) {
#pragma unroll
        for (int r = 0; r < 2; r++) {
            int row = arow0 + r * 64;
            float4 av = *(const float4*)(A + (size_t)asrc[r] * K + k0 + akq * 4);
            As[akq*4+0][row] = av.x;
            As[akq*4+1][row] = av.y;
            As[akq*4+2][row] = av.z;
            As[akq*4+3][row] = av.w;
        }
        {
            float4 bv = *(const float4*)(W + (size_t)bsrc * K + k0 + akq * 4);
            Bs[akq*4+0][brow] = bv.x;
            Bs[akq*4+1][brow] = bv.y;
            Bs[akq*4+2][brow] = bv.z;
            Bs[akq*4+3][brow] = bv.w;
        }
        __syncthreads();

#pragma unroll
        for (int kk = 0; kk < 16; kk++) {
            float af[8], bf[4];
#pragma unroll
            for (int i = 0; i < 8; i++) af[i] = As[kk][ty * 8 + i];
#pragma unroll
            for (int j = 0; j < 4; j++) bf[j] = Bs[kk][tx * 4 + j];
#pragma unroll
            for (int i = 0; i < 8; i++)
#pragma unroll
                for (int j = 0; j < 4; j++)
                    acc[i][j] = fmaf(af[i], bf[j], acc[i][j]);
        }
        __syncthreads();
    }

    // BN epilogue
#pragma unroll
    for (int j = 0; j < 4; j++) {
        int n = bn + tx * 4 + j;
        float sc = bn_g[n] * rsqrtf(bn_v[n] + BN_EPS);
        float bi = bn_b[n] - bn_m[n] * sc;
#pragma unroll
        for (int i = 0; i < 8; i++) {
            int m = bm + ty * 8 + i;
            C[(size_t)m * N + n] = fmaf(acc[i][j], sc, bi);
        }
    }
}

// ---------------------------------------------------------------------------
// Attention: one block per (b, h). 256 threads = 8 warps.
// S[q,n] = <q[q,:], k[n,:]> * SCALE + biases[h, bias_idxs[q,n]]
// P = softmax(S, axis=n);  out[q,d] = sum_n P[q,n]*v[n,d]; silu; store.
// ---------------------------------------------------------------------------
__global__ __launch_bounds__(256)
void attn_kernel(const float* __restrict__ kv, const float* __restrict__ q,
                 const float* __restrict__ biases, const int* __restrict__ bias_idxs,
                 float* __restrict__ ao)
{
    __shared__ float qs[NQTOK * KD];      // 784
    __shared__ float ks[NTOK * KD];       // 3136
    __shared__ float vs[NTOK * VD];       // 6272
    __shared__ float bias_h[NTOK];        // 196
    __shared__ float pbuf[8 * NTOK];      // 1568

    const int tid = threadIdx.x;
    const int b = blockIdx.x / HEADS;
    const int h = blockIdx.x - b * HEADS;

    // stage q
    for (int i = tid; i < NQTOK * KD; i += 256) {
        int qi = i / KD, d = i - qi * KD;
        qs[i] = q[(size_t)(b * NQTOK + qi) * KEYATTN + h * KD + d];
    }
    // stage k
    for (int i = tid; i < NTOK * KD; i += 256) {
        int n = i / KD, d = i - n * KD;
        ks[i] = kv[(size_t)(b * NTOK + n) * KVD + h * (KD + VD) + d];
    }
    // stage v
    for (int i = tid; i < NTOK * VD; i += 256) {
        int n = i / VD, d = i - n * VD;
        vs[i] = kv[(size_t)(b * NTOK + n) * KVD + h * (KD + VD) + KD + d];
    }
    for (int i = tid; i < NTOK; i += 256) bias_h[i] = biases[h * NTOK + i];
    __syncthreads();

    const int w = tid >> 5;
    const int l = tid & 31;

    for (int qq = w; qq < NQTOK; qq += 8) {
        float s[7];
        float mx = -1e30f;
#pragma unroll
        for (int it = 0; it < 7; it++) {
            int n = l + it * 32;
            float val = -1e30f;
            if (n < NTOK) {
                float a = 0.f;
#pragma unroll
                for (int d = 0; d < KD; d++)
                    a = fmaf(qs[qq * KD + d], ks[n * KD + d], a);
                val = fmaf(a, ATTNSCALE, bias_h[bias_idxs[qq * NTOK + n]]);
            }
            s[it] = val;
            mx = fmaxf(mx, val);
        }
#pragma unroll
        for (int o = 16; o > 0; o >>= 1)
            mx = fmaxf(mx, __shfl_xor_sync(0xffffffffu, mx, o));

        float sum = 0.f;
        float e[7];
#pragma unroll
        for (int it = 0; it < 7; it++) {
            int n = l + it * 32;
            float ev = (n < NTOK) ? __expf(s[it] - mx) : 0.f;
            e[it] = ev;
            sum += ev;
        }
#pragma unroll
        for (int o = 16; o > 0; o >>= 1)
            sum += __shfl_xor_sync(0xffffffffu, sum, o);
        float inv = 1.f / sum;
#pragma unroll
        for (int it = 0; it < 7; it++) {
            int n = l + it * 32;
            if (n < NTOK) pbuf[w * NTOK + n] = e[it] * inv;
        }
        __syncwarp();

        // out[qq, d] for d = lane
        float o = 0.f;
        const float* pr = &pbuf[w * NTOK];
#pragma unroll 4
        for (int n = 0; n < NTOK; n++)
            o = fmaf(pr[n], vs[n * VD + l], o);

        // silu
        float so = o / (1.f + __expf(-o));
        ao[(size_t)(b * NQTOK + qq) * VALATTN + h * VD + l] = so;
        __syncwarp();
    }
}

// ---------------------------------------------------------------------------
// Launch
// ---------------------------------------------------------------------------
extern "C" void kernel_launch(void* const* d_in, const int* in_sizes, int n_in,
                              void* d_out, int out_size)
{
    const float* x     = (const float*)d_in[0];
    const float* kv_w  = (const float*)d_in[1];
    const float* kv_g  = (const float*)d_in[2];
    const float* kv_b  = (const float*)d_in[3];
    const float* kv_m  = (const float*)d_in[4];
    const float* kv_v  = (const float*)d_in[5];
    const float* q_w   = (const float*)d_in[6];
    const float* q_g   = (const float*)d_in[7];
    const float* q_b   = (const float*)d_in[8];
    const float* q_m   = (const float*)d_in[9];
    const float* q_v   = (const float*)d_in[10];
    const float* pj_w  = (const float*)d_in[11];
    const float* pj_g  = (const float*)d_in[12];
    const float* pj_b  = (const float*)d_in[13];
    const float* pj_m  = (const float*)d_in[14];
    const float* pj_v  = (const float*)d_in[15];
    const float* biases    = (const float*)d_in[16];
    const int*   bias_idxs = (const int*)d_in[17];
    float* out = (float*)d_out;

    float *kv_buf, *q_buf, *ao_buf;
    cudaGetSymbolAddress((void**)&kv_buf, g_kv);
    cudaGetSymbolAddress((void**)&q_buf,  g_q);
    cudaGetSymbolAddress((void**)&ao_buf, g_ao);

    // GEMM1: kv = BN(x @ kv_w^T)   [50176 x 576]
    gemm_bn_kernel<false><<<dim3(KVD / 64, M1 / 128), 256>>>(
        x, kv_w, kv_g, kv_b, kv_m, kv_v, kv_buf, KVD);

    // GEMM2: q = BN(xq @ q_w^T)    [12544 x 192], gathered rows
    gemm_bn_kernel<true><<<dim3(KEYATTN / 64, M2 / 128), 256>>>(
        x, q_w, q_g, q_b, q_m, q_v, q_buf, KEYATTN);

    // Attention + softmax + silu   [3072 blocks]
    attn_kernel<<<BATCH * HEADS, 256>>>(kv_buf, q_buf, biases, bias_idxs, ao_buf);

    // GEMM3: out = BN(silu_attn @ pj_w^T)  [12544 x 512]
    gemm_bn_kernel<false><<<dim3(OUTDIM / 64, M2 / 128), 256>>>(
        ao_buf, pj_w, pj_g, pj_b, pj_m, pj_v, out, OUTDIM);
}